// round 7
// baseline (speedup 1.0000x reference)
#include <cuda_runtime.h>
#include <cuda_bf16.h>
#include <cstdint>

// Problem constants
#define BATCH   32
#define NATOMS  1024
#define PAD     1028       // plane stride: 16B-aligned, 1028 mod 32 = 4 -> distinct banks
#define RPB     8          // rows per block
#define THREADS 256
#define ROW_F4  768        // float4s per output row (1024*3/4)
#define ROW_B   12288      // bytes per output row

// Minimum-image wrap without the divide, bit-exact vs the reference's
// rintf(__fdiv_rn(d, L)) * L for |d| < L:
// rn(d/L) > 0.5 <=> d > L/2 for representable d; tie at d == L/2 -> rint = 0.
__device__ __forceinline__ float wrapmi(float d, float L, float hl)
{
    float r = d;
    if (d >  hl) r = d - L;
    if (d < -hl) r = d + L;
    return r;
}

__device__ __forceinline__ uint32_t smem_u32(const void* p)
{
    return (uint32_t)__cvta_generic_to_shared(p);
}

// Each block: one frame b, RPB consecutive i-rows. Rows are computed into a
// double-buffered SMEM staging area (STS.128, warp writes 512B contiguous ->
// conflict-free) and streamed to GMEM with cp.async.bulk (TMA path), which
// bypasses the per-thread L1/LSU store port that R3-R6 showed to be the
// binding pipe (~76% at 60us regardless of compute profile).
// Column mapping per float4 q (= s*256 + t) within a row: f0 = 4q,
// ja = f0/3, r = f0 mod 3; axes are the rotation (e0,e1,e2,e0) of (x,y,z)
// by r and atoms are ja (first 3-r comps) then ja+1. pj/L/H hoisted per s.
__global__ __launch_bounds__(THREADS)
void rij_min_image_kernel(const float* __restrict__ pos,
                          const float* __restrict__ cell,
                          float* __restrict__ out)
{
    __shared__ float sp[3 * PAD];                        // SoA planes, 12.3 KB
    __shared__ __align__(16) float4 stage[2][ROW_F4];    // 2 x 12 KB staging

    const int b  = blockIdx.y;
    const int i0 = blockIdx.x * RPB;
    const int t  = threadIdx.x;

    // Cooperative SoA fill, vectorized global reads.
    const float4* pb4 = (const float4*)(pos + (size_t)b * NATOMS * 3);
    #pragma unroll
    for (int v = t; v < (NATOMS * 3) / 4; v += THREADS) {
        const float4 w = pb4[v];
        const int f = 4 * v;
        sp[((f + 0) % 3) * PAD + (f + 0) / 3] = w.x;
        sp[((f + 1) % 3) * PAD + (f + 1) / 3] = w.y;
        sp[((f + 2) % 3) * PAD + (f + 2) / 3] = w.z;
        sp[((f + 3) % 3) * PAD + (f + 3) / 3] = w.w;
    }

    // Box lengths from the cell diagonal; L/2 exact in binary FP.
    const float Lx = cell[(size_t)b * 9 + 0];
    const float Ly = cell[(size_t)b * 9 + 4];
    const float Lz = cell[(size_t)b * 9 + 8];
    const float Hx = 0.5f * Lx, Hy = 0.5f * Ly, Hz = 0.5f * Lz;

    __syncthreads();

    // Hoist per-s column-atom data and rotated box constants into registers.
    float pj0[3], pj1[3], pj2[3], pj3[3];
    float L0[3], L1[3], L2[3], H0[3], H1[3], H2[3];
    int   E0[3], E1[3], E2[3];
    #pragma unroll
    for (int s = 0; s < 3; ++s) {
        const int q  = s * THREADS + t;     // float4 index in row, 0..767
        const int f0 = 4 * q;
        const int ja = f0 / 3;              // <= 1022
        const int r  = f0 - 3 * ja;

        const int e0 = r;
        const int e1 = (r == 2) ? 0 : r + 1;
        const int e2 = (r == 0) ? 2 : r - 1;
        E0[s] = e0; E1[s] = e1; E2[s] = e2;

        const int a1 = (r >= 2) ? ja + 1 : ja;
        const int a2 = (r >= 1) ? ja + 1 : ja;

        pj0[s] = sp[e0 * PAD + ja];
        pj1[s] = sp[e1 * PAD + a1];
        pj2[s] = sp[e2 * PAD + a2];
        pj3[s] = sp[e0 * PAD + ja + 1];

        L0[s] = (r == 0) ? Lx : ((r == 1) ? Ly : Lz);
        L1[s] = (r == 0) ? Ly : ((r == 1) ? Lz : Lx);
        L2[s] = (r == 0) ? Lz : ((r == 1) ? Lx : Ly);
        H0[s] = (r == 0) ? Hx : ((r == 1) ? Hy : Hz);
        H1[s] = (r == 0) ? Hy : ((r == 1) ? Hz : Hx);
        H2[s] = (r == 0) ? Hz : ((r == 1) ? Hx : Hy);
    }

    float* gdst0 = out + ((size_t)b * NATOMS + i0) * NATOMS * 3;

    #pragma unroll
    for (int k = 0; k < RPB; ++k) {
        // Before reusing buffer (k & 1), wait until the bulk store issued
        // two rows ago has finished READING it.
        if (k >= 2) {
            if (t == 0)
                asm volatile("cp.async.bulk.wait_group.read 1;" ::: "memory");
            __syncthreads();
        }

        float4* buf = stage[k & 1];
        const int i = i0 + k;

        #pragma unroll
        for (int s = 0; s < 3; ++s) {
            const float p0 = sp[E0[s] * PAD + i];
            const float p1 = sp[E1[s] * PAD + i];
            const float p2 = sp[E2[s] * PAD + i];

            float4 v;
            v.x = wrapmi(p0 - pj0[s], L0[s], H0[s]);
            v.y = wrapmi(p1 - pj1[s], L1[s], H1[s]);
            v.z = wrapmi(p2 - pj2[s], L2[s], H2[s]);
            v.w = wrapmi(p0 - pj3[s], L0[s], H0[s]);

            buf[s * THREADS + t] = v;   // STS.128, warp-contiguous 512B
        }

        __syncthreads();   // all STS for this row complete

        if (t == 0) {
            // Order generic-proxy STS before the async-proxy bulk read,
            // then issue the 12KB row store via the TMA path.
            asm volatile("fence.proxy.async.shared::cta;" ::: "memory");
            const uint32_t src = smem_u32(buf);
            asm volatile(
                "cp.async.bulk.global.shared::cta.bulk_group [%0], [%1], %2;"
                :: "l"(gdst0 + (size_t)k * (NATOMS * 3)), "r"(src), "r"(ROW_B)
                : "memory");
            asm volatile("cp.async.bulk.commit_group;" ::: "memory");
        }
    }

    // Drain remaining bulk stores before exit (cheap; kernel boundary would
    // also guarantee completion, this makes it explicit).
    if (t == 0)
        asm volatile("cp.async.bulk.wait_group 0;" ::: "memory");
}

extern "C" void kernel_launch(void* const* d_in, const int* in_sizes, int n_in,
                              void* d_out, int out_size)
{
    const float* positions = (const float*)d_in[0];  // (32, 1024, 3)
    const float* cell      = (const float*)d_in[1];  // (32, 3, 3)
    float* out             = (float*)d_out;          // (32, 1024, 1024, 3)

    dim3 grid(NATOMS / RPB, BATCH);   // (128, 32) = 4096 blocks
    rij_min_image_kernel<<<grid, THREADS>>>(positions, cell, out);
}

// round 8
// speedup vs baseline: 1.0399x; 1.0399x over previous
#include <cuda_runtime.h>
#include <cuda_bf16.h>

// Problem constants
#define BATCH   32
#define NATOMS  1024
#define PAD     1028       // plane stride: 1028 mod 32 = 4 -> planes on distinct banks
#define ITILE   4          // output rows per block (best-measured config, R3)
#define THREADS 256

// Minimum-image wrap without the divide, bit-exact vs the reference's
// rintf(__fdiv_rn(d, L)) * L for |d| < L:
// rn(d/L) > 0.5 <=> d > L/2 for representable d; tie at d == L/2 -> rint = 0.
__device__ __forceinline__ float wrapmi(float d, float L, float hl)
{
    float r = d;
    if (d >  hl) r = d - L;
    if (d < -hl) r = d + L;
    return r;
}

// Each block: one frame b, ITILE consecutive i-rows.
// Row = 3072 floats = 768 float4s. Thread t stores float4 q = s*256 + t for
// s = 0..2 -> every warp STG.128 covers a contiguous 512B span (coalesced,
// full 128B lines -> pure write stream, no RMW reads).
// Component c of float4 q maps to atom (4q+c)/3, axis (4q+c)%3; with
// r = 4q mod 3 the axes are the rotation (e0,e1,e2,e0) of (x,y,z) and the
// atoms are ja (first 3-r components) then ja+1 — resolved once per s, so
// the inner loop computes exactly 4 wraps per 16B stored (no overcompute,
// no per-element SEL chains).
// R3-R7 established the binding constraint is the HBM write ceiling
// (~6.7 TB/s delivered = 83% of spec across 4 different store paths); this
// kernel is the merged best-of configuration.
__global__ __launch_bounds__(THREADS)
void rij_min_image_kernel(const float* __restrict__ pos,
                          const float* __restrict__ cell,
                          float* __restrict__ out)
{
    __shared__ float sp[3 * PAD];      // SoA planes: x @0, y @PAD, z @2*PAD

    const int b  = blockIdx.y;
    const int i0 = blockIdx.x * ITILE;

    // Cooperative SoA fill, vectorized global reads (L2-resident after wave 1).
    const float4* pb4 = (const float4*)(pos + (size_t)b * NATOMS * 3);
    #pragma unroll
    for (int v = threadIdx.x; v < (NATOMS * 3) / 4; v += THREADS) {
        const float4 w = pb4[v];
        const int f = 4 * v;
        sp[((f + 0) % 3) * PAD + (f + 0) / 3] = w.x;
        sp[((f + 1) % 3) * PAD + (f + 1) / 3] = w.y;
        sp[((f + 2) % 3) * PAD + (f + 2) / 3] = w.z;
        sp[((f + 3) % 3) * PAD + (f + 3) / 3] = w.w;
    }

    // Box lengths from the cell diagonal; L/2 exact in binary FP.
    const float Lx = cell[(size_t)b * 9 + 0];
    const float Ly = cell[(size_t)b * 9 + 4];
    const float Lz = cell[(size_t)b * 9 + 8];
    const float Hx = 0.5f * Lx, Hy = 0.5f * Ly, Hz = 0.5f * Lz;

    __syncthreads();

    float* orow = out + ((size_t)b * NATOMS + i0) * NATOMS * 3;

    #pragma unroll
    for (int s = 0; s < 3; ++s) {
        const int q  = s * THREADS + threadIdx.x;   // float4 index in row
        const int f0 = 4 * q;
        const int ja = f0 / 3;                      // first atom (<= 1022)
        const int r  = f0 - 3 * ja;                 // 0, 1, or 2

        // Rotated axes: e0 = r, e1 = (r+1) mod 3, e2 = (r+2) mod 3.
        const int e0 = r;
        const int e1 = (r == 2) ? 0 : r + 1;
        const int e2 = (r == 0) ? 2 : r - 1;

        // Atoms per component k: ja for k < 3-r, else ja+1.
        const int a1 = (r >= 2) ? ja + 1 : ja;      // k=1
        const int a2 = (r >= 1) ? ja + 1 : ja;      // k=2

        // Column-atom coordinates (4 scalar LDS per s, reused over ITILE rows).
        const float pj0 = sp[e0 * PAD + ja];
        const float pj1 = sp[e1 * PAD + a1];
        const float pj2 = sp[e2 * PAD + a2];
        const float pj3 = sp[e0 * PAD + ja + 1];

        // Per-component box length / half-box, resolved once per s.
        const float L0 = (r == 0) ? Lx : ((r == 1) ? Ly : Lz);
        const float L1 = (r == 0) ? Ly : ((r == 1) ? Lz : Lx);
        const float L2 = (r == 0) ? Lz : ((r == 1) ? Lx : Ly);
        const float H0 = (r == 0) ? Hx : ((r == 1) ? Hy : Hz);
        const float H1 = (r == 0) ? Hy : ((r == 1) ? Hz : Hx);
        const float H2 = (r == 0) ? Hz : ((r == 1) ? Hx : Hy);

        // Row-atom planes, rotated: immediate-offset LDS inside the loop.
        const float* pe0 = sp + e0 * PAD + i0;
        const float* pe1 = sp + e1 * PAD + i0;
        const float* pe2 = sp + e2 * PAD + i0;

        float4* dst = (float4*)orow + q;            // + ii*768 via immediates

        #pragma unroll
        for (int ii = 0; ii < ITILE; ++ii) {
            const float p0 = pe0[ii];
            const float p1 = pe1[ii];
            const float p2 = pe2[ii];

            float4 v;
            v.x = wrapmi(p0 - pj0, L0, H0);
            v.y = wrapmi(p1 - pj1, L1, H1);
            v.z = wrapmi(p2 - pj2, L2, H2);
            v.w = wrapmi(p0 - pj3, L0, H0);

            __stcs(dst + (size_t)ii * (NATOMS * 3 / 4), v);
        }
    }
}

extern "C" void kernel_launch(void* const* d_in, const int* in_sizes, int n_in,
                              void* d_out, int out_size)
{
    const float* positions = (const float*)d_in[0];  // (32, 1024, 3)
    const float* cell      = (const float*)d_in[1];  // (32, 3, 3)
    float* out             = (float*)d_out;          // (32, 1024, 1024, 3)

    dim3 grid(NATOMS / ITILE, BATCH);   // (256, 32) = 8192 blocks
    rij_min_image_kernel<<<grid, THREADS>>>(positions, cell, out);
}